// round 12
// baseline (speedup 1.0000x reference)
#include <cuda_runtime.h>
#include <cuda_bf16.h>
#include <math.h>
#include <stdint.h>

#define NUM_CLASSES 19
#define KPC 100
#define NA 1900
#define NA_PAD 1920
#define NMEM 20000
#define NCOLS 21900
#define NC_PAD 22016
#define DIMS 256
#define HW 16384
#define LBLK 1024
#define NLBLK 128
#define ROW_TILES 15
#define COL_CHUNKS 9
#define NSUB128 172
#define TEMP_INV 10.0f
#define L2E10 14.426950408889634f
#define LOSS_SCALE 1.4285714285714286f

// -------------------- device scratch --------------------
__device__ int g_lab64;
__device__ int g_idx[NA];
__device__ __align__(16) __nv_bfloat16 g_A[NA_PAD * DIMS];
__device__ __align__(16) __nv_bfloat16 g_C[NC_PAD * DIMS];
__device__ __align__(16) int g_clab[NC_PAD];
__device__ float g_Sp[NA_PAD * COL_CHUNKS];
__device__ float g_Pp[NA_PAD * COL_CHUNKS];

__device__ __forceinline__ int load_label(const void* p, int i) {
    if (g_lab64) return (int)((const long long*)p)[i];
    return ((const int*)p)[i];
}

// MUFU-based exp-and-accumulate: S += 2^(acc*10*log2e), P += acc if labels match.
__device__ __forceinline__ void ep_core(float acc_v, int labv, int rl, float& S, float& P) {
    float e;
    asm("ex2.approx.f32 %0, %1;" : "=f"(e) : "f"(acc_v * L2E10));
    S += e;
    if (labv == rl) P += acc_v;
}

__device__ __forceinline__ void mma_bf16(float* d, const unsigned* a, const unsigned* b) {
    asm volatile(
        "mma.sync.aligned.m16n8k16.row.col.f32.bf16.bf16.f32 "
        "{%0,%1,%2,%3}, {%4,%5,%6,%7}, {%8,%9}, {%0,%1,%2,%3};\n"
        : "+f"(d[0]), "+f"(d[1]), "+f"(d[2]), "+f"(d[3])
        : "r"(a[0]), "r"(a[1]), "r"(a[2]), "r"(a[3]), "r"(b[0]), "r"(b[1]));
}

__device__ __forceinline__ void ldsm_x4(unsigned& r0, unsigned& r1, unsigned& r2,
                                        unsigned& r3, unsigned addr) {
    asm volatile("ldmatrix.sync.aligned.m8n8.x4.shared.b16 {%0,%1,%2,%3}, [%4];"
                 : "=r"(r0), "=r"(r1), "=r"(r2), "=r"(r3) : "r"(addr));
}

__device__ __forceinline__ void cpasync16(unsigned s_addr, const void* g_ptr) {
    asm volatile("cp.async.cg.shared.global [%0], [%1], 16;" :: "r"(s_addr), "l"(g_ptr));
}
#define CP_COMMIT() asm volatile("cp.async.commit_group;")
#define CP_WAIT0()  asm volatile("cp.async.wait_group 0;" ::: "memory")

// -------------------- fused sampling: detect + sequential ballot ranking ------------
__global__ void k_sample(const int* lab32, const void* labels) {
    __shared__ int slab[LBLK];
    __shared__ int sbad;
    __shared__ int squit;
    int tid  = threadIdx.x;
    int lane = tid & 31;
    int w    = tid >> 5;

    if (tid == 0) sbad = 0;
    __syncthreads();
    if (lab32[2 * tid + 1] != 0) sbad = 1;
    __syncthreads();
    const int is64 = (sbad == 0) ? 1 : 0;
    if (tid == 0) g_lab64 = is64;

    int r = 0;
    unsigned below = (1u << lane) - 1u;

    for (int c = 0; c < NLBLK; c++) {
        int base = c * LBLK;
        int v;
        if (is64) v = (int)((const long long*)labels)[base + tid];
        else      v = ((const int*)labels)[base + tid];
        if (tid == 0) squit = 1;
        slab[tid] = v;
        __syncthreads();

        if (w < NUM_CLASSES && r < KPC) {
            #pragma unroll 4
            for (int s = 0; s < 32; s++) {
                int lv = slab[s * 32 + lane];
                unsigned m = __ballot_sync(0xffffffffu, lv == w);
                if (lv == w) {
                    int rank = r + __popc(m & below);
                    if (rank < KPC) g_idx[w * KPC + rank] = base + s * 32 + lane;
                }
                r += __popc(m);
                if (r >= KPC) break;
            }
        }
        if (w < NUM_CLASSES && lane == 0 && r < KPC) squit = 0;
        __syncthreads();
        if (squit) break;
    }
}

// -------------------- gather + normalize anchors (+ anchor labels) --------------------
__global__ void k_anchor(const float* __restrict__ pf) {
    int wid  = threadIdx.x >> 5;
    int lane = threadIdx.x & 31;
    int n = blockIdx.x * 8 + wid;
    float v[8];
    if (n < NA) {
        int idx = g_idx[n];
        int b   = idx >> 14;
        int rem = idx & (HW - 1);
        const float* src = pf + (size_t)b * (DIMS * HW) + rem;
        #pragma unroll
        for (int j = 0; j < 8; j++)
            v[j] = src[(size_t)(lane + 32 * j) * HW];
    } else {
        #pragma unroll
        for (int j = 0; j < 8; j++) v[j] = 0.f;
    }
    float ss = 0.f;
    #pragma unroll
    for (int j = 0; j < 8; j++) ss += v[j] * v[j];
    #pragma unroll
    for (int o = 16; o; o >>= 1) ss += __shfl_xor_sync(0xffffffffu, ss, o);
    float sc = (n < NA) ? (1.f / fmaxf(sqrtf(ss), 1e-12f)) : 0.f;
    #pragma unroll
    for (int j = 0; j < 8; j++) {
        __nv_bfloat16 o16 = __float2bfloat16(v[j] * sc);
        int d = lane + 32 * j;
        g_A[n * DIMS + d] = o16;
        g_C[n * DIMS + d] = o16;
    }
    if (lane == 0 && n < NA) g_clab[n] = n / KPC;
}

// -------------------- normalize memory feats (+ contrast labels) --------------------
__global__ void k_mem(const float* __restrict__ mf, const void* mlab) {
    int wid  = threadIdx.x >> 5;
    int lane = threadIdx.x & 31;
    int m = blockIdx.x * 8 + wid;
    if (m >= NC_PAD - NA) return;
    float v[8];
    if (m < NMEM) {
        const float* src = mf + (size_t)m * DIMS;
        #pragma unroll
        for (int j = 0; j < 8; j++) v[j] = src[lane + 32 * j];
    } else {
        #pragma unroll
        for (int j = 0; j < 8; j++) v[j] = 0.f;
    }
    float ss = 0.f;
    #pragma unroll
    for (int j = 0; j < 8; j++) ss += v[j] * v[j];
    #pragma unroll
    for (int o = 16; o; o >>= 1) ss += __shfl_xor_sync(0xffffffffu, ss, o);
    float sc = (m < NMEM) ? (1.f / fmaxf(sqrtf(ss), 1e-12f)) : 0.f;
    #pragma unroll
    for (int j = 0; j < 8; j++)
        g_C[(size_t)(NA + m) * DIMS + lane + 32 * j] = __float2bfloat16(v[j] * sc);
    if (lane == 0)
        g_clab[NA + m] = (m < NMEM) ? load_label(mlab, m) : -1;
}

// -------------------- fused GEMM + softmax reductions -----------------
// Block tile 128 rows x 128 cols, warp tile 32x64 (4x2 warps), 1 CTA/SM,
// double-buffered Cs via cp.async.
extern __shared__ char smem_raw[];

#define AS_BYTES (128 * 264 * 2)
#define CS_BYTES (128 * 264 * 2)
#define OFF_CS0  AS_BYTES
#define OFF_CS1  (AS_BYTES + CS_BYTES)
#define OFF_CLAB (AS_BYTES + 2 * CS_BYTES)              // two buffers of 128 ints
#define OFF_REDS (OFF_CLAB + 2 * 512)
#define OFF_REDP (OFF_REDS + 1024)
#define SMEM_BYTES (OFF_REDP + 1024)

__global__ void __launch_bounds__(256, 1) k_main() {
    __nv_bfloat16* As = (__nv_bfloat16*)smem_raw;
    float* redS = (float*)(smem_raw + OFF_REDS);
    float* redP = (float*)(smem_raw + OFF_REDP);
    int*   clab_sm = (int*)(smem_raw + OFF_CLAB);        // [2][128]

    const int tid     = threadIdx.x;
    const int chunk   = blockIdx.x;
    const int rowbase = blockIdx.y * 128;
    const int lane = tid & 31;
    const int w    = tid >> 5;
    const int wr   = w >> 1;       // 0..3
    const int wc   = w & 1;        // 0..1 (64-col half)
    const int g    = lane >> 2;
    const int t2   = (lane & 3) * 2;

    unsigned smu = (unsigned)__cvta_generic_to_shared(smem_raw);
    unsigned as_u32 = smu;

    // A tile [128][256] via cp.async
    #pragma unroll
    for (int it = 0; it < 16; it++) {
        int lin = tid + it * 256;
        int row = lin >> 5;
        int kv  = lin & 31;
        cpasync16(as_u32 + (row * 264 + kv * 8) * 2,
                  g_A + (size_t)(rowbase + row) * DIMS + kv * 8);
    }
    // first Cs subtile into buffer 0
    {
        const int colbase = chunk * 128;
        #pragma unroll
        for (int it = 0; it < 16; it++) {
            int lin = tid + it * 256;
            int row = lin >> 5;
            int kv  = lin & 31;
            cpasync16(smu + OFF_CS0 + (row * 264 + kv * 8) * 2,
                      g_C + (size_t)(colbase + row) * DIMS + kv * 8);
        }
        if (tid < 32) cpasync16(smu + OFF_CLAB + tid * 16, g_clab + colbase + tid * 4);
    }
    CP_COMMIT();

    // ldmatrix lane addresses
    unsigned aAddr[2], bOff[4];
    {
        int arow = (lane & 7) + ((lane >> 3) & 1) * 8;
        int acol = (lane >> 4) * 8;
        #pragma unroll
        for (int mb = 0; mb < 2; mb++)
            aAddr[mb] = as_u32 + ((wr * 32 + mb * 16 + arow) * 264 + acol) * 2;
        int brow = ((lane >> 4) & 1) * 8 + (lane & 7);
        int bcol = ((lane >> 3) & 1) * 8;
        #pragma unroll
        for (int pr = 0; pr < 4; pr++)
            bOff[pr] = ((wc * 64 + pr * 16 + brow) * 264 + bcol) * 2;
    }

    float Sacc[2][2] = {{0.f, 0.f}, {0.f, 0.f}};
    float Pacc[2][2] = {{0.f, 0.f}, {0.f, 0.f}};
    int rlab[2][2], grow[2][2];
    #pragma unroll
    for (int mb = 0; mb < 2; mb++)
        #pragma unroll
        for (int p = 0; p < 2; p++) {
            int r = rowbase + wr * 32 + mb * 16 + g + 8 * p;
            grow[mb][p] = r;
            rlab[mb][p] = (r < NA) ? (r / KPC) : -2;
        }

    CP_WAIT0();
    __syncthreads();

    int i = 0;
    for (int s = chunk; s < NSUB128; s += COL_CHUNKS, i++) {
        const int colbase = s * 128;
        const int cur = i & 1;
        const unsigned csBase = smu + (cur ? OFF_CS1 : OFF_CS0);
        const bool edge = (colbase + 128 > NCOLS) || (colbase == rowbase);

        // prefetch next subtile into the other buffer
        const int ns = s + COL_CHUNKS;
        if (ns < NSUB128) {
            const int ncb = ns * 128;
            const unsigned nxtBase = smu + (cur ? OFF_CS0 : OFF_CS1);
            #pragma unroll
            for (int it = 0; it < 16; it++) {
                int lin = tid + it * 256;
                int row = lin >> 5;
                int kv  = lin & 31;
                cpasync16(nxtBase + (row * 264 + kv * 8) * 2,
                          g_C + (size_t)(ncb + row) * DIMS + kv * 8);
            }
            if (tid < 32)
                cpasync16(smu + OFF_CLAB + (cur ^ 1) * 512 + tid * 16,
                          g_clab + ncb + tid * 4);
        }
        CP_COMMIT();

        float acc[2][8][4];
        #pragma unroll
        for (int mb = 0; mb < 2; mb++)
            #pragma unroll
            for (int nb = 0; nb < 8; nb++)
                #pragma unroll
                for (int q = 0; q < 4; q++) acc[mb][nb][q] = 0.f;

        #pragma unroll
        for (int k = 0; k < DIMS; k += 16) {
            unsigned a[2][4], b[8][2];
            #pragma unroll
            for (int mb = 0; mb < 2; mb++)
                ldsm_x4(a[mb][0], a[mb][1], a[mb][2], a[mb][3], aAddr[mb] + k * 2);
            #pragma unroll
            for (int pr = 0; pr < 4; pr++)
                ldsm_x4(b[2 * pr][0], b[2 * pr][1], b[2 * pr + 1][0], b[2 * pr + 1][1],
                        csBase + bOff[pr] + k * 2);
            #pragma unroll
            for (int mb = 0; mb < 2; mb++)
                #pragma unroll
                for (int nb = 0; nb < 8; nb++)
                    mma_bf16(acc[mb][nb], a[mb], b[nb]);
        }

        int labreg[16];
        #pragma unroll
        for (int nb = 0; nb < 8; nb++)
            #pragma unroll
            for (int e = 0; e < 2; e++)
                labreg[nb * 2 + e] = clab_sm[cur * 128 + wc * 64 + nb * 8 + t2 + e];

        if (!edge) {
            #pragma unroll
            for (int mb = 0; mb < 2; mb++)
                #pragma unroll
                for (int nb = 0; nb < 8; nb++)
                    #pragma unroll
                    for (int p = 0; p < 2; p++)
                        #pragma unroll
                        for (int e = 0; e < 2; e++)
                            ep_core(acc[mb][nb][2 * p + e], labreg[nb * 2 + e],
                                    rlab[mb][p], Sacc[mb][p], Pacc[mb][p]);
        } else {
            #pragma unroll
            for (int mb = 0; mb < 2; mb++)
                #pragma unroll
                for (int nb = 0; nb < 8; nb++) {
                    int colb = wc * 64 + nb * 8 + t2;
                    #pragma unroll
                    for (int p = 0; p < 2; p++)
                        #pragma unroll
                        for (int e = 0; e < 2; e++) {
                            int gcol = colbase + colb + e;
                            if (gcol < NCOLS && gcol != grow[mb][p])
                                ep_core(acc[mb][nb][2 * p + e], labreg[nb * 2 + e],
                                        rlab[mb][p], Sacc[mb][p], Pacc[mb][p]);
                        }
                }
        }

        CP_WAIT0();
        __syncthreads();    // all warps done with cur buffer; next buffer resident
    }

    #pragma unroll
    for (int mb = 0; mb < 2; mb++)
        #pragma unroll
        for (int p = 0; p < 2; p++) {
            float sv = Sacc[mb][p], pv = Pacc[mb][p];
            sv += __shfl_xor_sync(0xffffffffu, sv, 1);
            sv += __shfl_xor_sync(0xffffffffu, sv, 2);
            pv += __shfl_xor_sync(0xffffffffu, pv, 1);
            pv += __shfl_xor_sync(0xffffffffu, pv, 2);
            if ((lane & 3) == 0) {
                int row = wr * 32 + mb * 16 + g + 8 * p;
                redS[row * 2 + wc] = sv;
                redP[row * 2 + wc] = pv;
            }
        }
    __syncthreads();
    if (tid < 128) {
        int r = rowbase + tid;
        g_Sp[r * COL_CHUNKS + chunk] = redS[tid * 2] + redS[tid * 2 + 1];
        g_Pp[r * COL_CHUNKS + chunk] = redP[tid * 2] + redP[tid * 2 + 1];
    }
}

// -------------------- final scalar reduction --------------------
__global__ void k_final(const void* mlab, float* out) {
    __shared__ int scnt[NUM_CLASSES];
    __shared__ float wsum[32];
    int t = threadIdx.x;
    int lane = t & 31, wid = t >> 5;
    if (t < NUM_CLASSES) scnt[t] = 0;
    __syncthreads();
    for (int i = t; i < NMEM; i += 1024)
        atomicAdd(&scnt[load_label(mlab, i)], 1);
    __syncthreads();
    float local = 0.f;
    for (int n = t; n < NA; n += 1024) {
        float S = 0.f, P = 0.f;
        #pragma unroll
        for (int ch = 0; ch < COL_CHUNKS; ch++) {
            S += g_Sp[n * COL_CHUNKS + ch];
            P += g_Pp[n * COL_CHUNKS + ch];
        }
        float cnt = (float)(KPC - 1 + scnt[n / KPC]);
        local += (TEMP_INV * P - cnt * logf(S + 1e-12f)) / cnt;
    }
    #pragma unroll
    for (int o = 16; o; o >>= 1) local += __shfl_xor_sync(0xffffffffu, local, o);
    if (lane == 0) wsum[wid] = local;
    __syncthreads();
    if (t < 32) {
        float v = wsum[t];
        #pragma unroll
        for (int o = 16; o; o >>= 1) v += __shfl_xor_sync(0xffffffffu, v, o);
        if (t == 0) out[0] = -LOSS_SCALE * v / (float)NA;
    }
}

// -------------------- launch --------------------
extern "C" void kernel_launch(void* const* d_in, const int* in_sizes, int n_in,
                              void* d_out, int out_size) {
    (void)in_sizes; (void)n_in; (void)out_size;
    const float* pf   = (const float*)d_in[0];
    const void*  lab  = d_in[1];
    const float* mf   = (const float*)d_in[2];
    const void*  mlab = d_in[3];
    float* out = (float*)d_out;

    cudaFuncSetAttribute(k_main, cudaFuncAttributeMaxDynamicSharedMemorySize, SMEM_BYTES);

    k_sample<<<1, 1024>>>((const int*)lab, lab);
    k_anchor<<<NA_PAD / 8, 256>>>(pf);
    k_mem<<<(NC_PAD - NA + 7) / 8, 256>>>(mf, mlab);
    k_main<<<dim3(COL_CHUNKS, ROW_TILES), 256, SMEM_BYTES>>>();
    k_final<<<1, 1024>>>(mlab, out);
}

// round 13
// speedup vs baseline: 1.0022x; 1.0022x over previous
#include <cuda_runtime.h>
#include <cuda_bf16.h>
#include <math.h>
#include <stdint.h>

#define NUM_CLASSES 19
#define KPC 100
#define NA 1900
#define NA_PAD 1920
#define NMEM 20000
#define NCOLS 21900
#define NC_PAD 22016
#define DIMS 256
#define HW 16384
#define LBLK 1024
#define NLBLK 128
#define ROW_TILES 15
#define COL_CHUNKS 9
#define NSUB128 172
#define TEMP_INV 10.0f
#define L2E10 14.426950408889634f
#define LOSS_SCALE 1.4285714285714286f

// -------------------- device scratch --------------------
__device__ int g_lab64;
__device__ int g_idx[NA];
__device__ __align__(16) __nv_bfloat16 g_A[NA_PAD * DIMS];
__device__ __align__(16) __nv_bfloat16 g_C[NC_PAD * DIMS];
__device__ __align__(16) int g_clab[NC_PAD];
__device__ float g_Sp[NA_PAD * COL_CHUNKS];
__device__ float g_Pp[NA_PAD * COL_CHUNKS];

__device__ __forceinline__ int load_label(const void* p, int i) {
    if (g_lab64) return (int)((const long long*)p)[i];
    return ((const int*)p)[i];
}

// MUFU-based exp-and-accumulate: S += 2^(acc*10*log2e), P += acc if labels match.
__device__ __forceinline__ void ep_core(float acc_v, int labv, int rl, float& S, float& P) {
    float e;
    asm("ex2.approx.f32 %0, %1;" : "=f"(e) : "f"(acc_v * L2E10));
    S += e;
    if (labv == rl) P += acc_v;
}

__device__ __forceinline__ void mma_bf16(float* d, const unsigned* a, const unsigned* b) {
    asm volatile(
        "mma.sync.aligned.m16n8k16.row.col.f32.bf16.bf16.f32 "
        "{%0,%1,%2,%3}, {%4,%5,%6,%7}, {%8,%9}, {%0,%1,%2,%3};\n"
        : "+f"(d[0]), "+f"(d[1]), "+f"(d[2]), "+f"(d[3])
        : "r"(a[0]), "r"(a[1]), "r"(a[2]), "r"(a[3]), "r"(b[0]), "r"(b[1]));
}

__device__ __forceinline__ void ldsm_x4(unsigned& r0, unsigned& r1, unsigned& r2,
                                        unsigned& r3, unsigned addr) {
    asm volatile("ldmatrix.sync.aligned.m8n8.x4.shared.b16 {%0,%1,%2,%3}, [%4];"
                 : "=r"(r0), "=r"(r1), "=r"(r2), "=r"(r3) : "r"(addr));
}

__device__ __forceinline__ void cpasync16(unsigned s_addr, const void* g_ptr) {
    asm volatile("cp.async.cg.shared.global [%0], [%1], 16;" :: "r"(s_addr), "l"(g_ptr));
}
#define CP_COMMIT() asm volatile("cp.async.commit_group;")
#define CP_WAIT0()  asm volatile("cp.async.wait_group 0;" ::: "memory")

// -------------------- fused sampling --------------------
__global__ void k_sample(const int* lab32, const void* labels) {
    __shared__ int slab[LBLK];
    __shared__ int sbad;
    __shared__ int squit;
    int tid  = threadIdx.x;
    int lane = tid & 31;
    int w    = tid >> 5;

    if (tid == 0) sbad = 0;
    __syncthreads();
    if (lab32[2 * tid + 1] != 0) sbad = 1;
    __syncthreads();
    const int is64 = (sbad == 0) ? 1 : 0;
    if (tid == 0) g_lab64 = is64;

    int r = 0;
    unsigned below = (1u << lane) - 1u;

    for (int c = 0; c < NLBLK; c++) {
        int base = c * LBLK;
        int v;
        if (is64) v = (int)((const long long*)labels)[base + tid];
        else      v = ((const int*)labels)[base + tid];
        if (tid == 0) squit = 1;
        slab[tid] = v;
        __syncthreads();

        if (w < NUM_CLASSES && r < KPC) {
            #pragma unroll 4
            for (int s = 0; s < 32; s++) {
                int lv = slab[s * 32 + lane];
                unsigned m = __ballot_sync(0xffffffffu, lv == w);
                if (lv == w) {
                    int rank = r + __popc(m & below);
                    if (rank < KPC) g_idx[w * KPC + rank] = base + s * 32 + lane;
                }
                r += __popc(m);
                if (r >= KPC) break;
            }
        }
        if (w < NUM_CLASSES && lane == 0 && r < KPC) squit = 0;
        __syncthreads();
        if (squit) break;
    }
}

// -------------------- gather + normalize anchors --------------------
__global__ void k_anchor(const float* __restrict__ pf) {
    int wid  = threadIdx.x >> 5;
    int lane = threadIdx.x & 31;
    int n = blockIdx.x * 8 + wid;
    float v[8];
    if (n < NA) {
        int idx = g_idx[n];
        int b   = idx >> 14;
        int rem = idx & (HW - 1);
        const float* src = pf + (size_t)b * (DIMS * HW) + rem;
        #pragma unroll
        for (int j = 0; j < 8; j++)
            v[j] = src[(size_t)(lane + 32 * j) * HW];
    } else {
        #pragma unroll
        for (int j = 0; j < 8; j++) v[j] = 0.f;
    }
    float ss = 0.f;
    #pragma unroll
    for (int j = 0; j < 8; j++) ss += v[j] * v[j];
    #pragma unroll
    for (int o = 16; o; o >>= 1) ss += __shfl_xor_sync(0xffffffffu, ss, o);
    float sc = (n < NA) ? (1.f / fmaxf(sqrtf(ss), 1e-12f)) : 0.f;
    #pragma unroll
    for (int j = 0; j < 8; j++) {
        __nv_bfloat16 o16 = __float2bfloat16(v[j] * sc);
        int d = lane + 32 * j;
        g_A[n * DIMS + d] = o16;
        g_C[n * DIMS + d] = o16;
    }
    if (lane == 0 && n < NA) g_clab[n] = n / KPC;
}

// -------------------- normalize memory feats --------------------
__global__ void k_mem(const float* __restrict__ mf, const void* mlab) {
    int wid  = threadIdx.x >> 5;
    int lane = threadIdx.x & 31;
    int m = blockIdx.x * 8 + wid;
    if (m >= NC_PAD - NA) return;
    float v[8];
    if (m < NMEM) {
        const float* src = mf + (size_t)m * DIMS;
        #pragma unroll
        for (int j = 0; j < 8; j++) v[j] = src[lane + 32 * j];
    } else {
        #pragma unroll
        for (int j = 0; j < 8; j++) v[j] = 0.f;
    }
    float ss = 0.f;
    #pragma unroll
    for (int j = 0; j < 8; j++) ss += v[j] * v[j];
    #pragma unroll
    for (int o = 16; o; o >>= 1) ss += __shfl_xor_sync(0xffffffffu, ss, o);
    float sc = (m < NMEM) ? (1.f / fmaxf(sqrtf(ss), 1e-12f)) : 0.f;
    #pragma unroll
    for (int j = 0; j < 8; j++)
        g_C[(size_t)(NA + m) * DIMS + lane + 32 * j] = __float2bfloat16(v[j] * sc);
    if (lane == 0)
        g_clab[NA + m] = (m < NMEM) ? load_label(mlab, m) : -1;
}

// -------------------- fused GEMM + softmax reductions -----------------
// Block tile 128 rows x 128 cols, 512 threads (4x4 warps of 32x32), 1 CTA/SM,
// double-buffered Cs via cp.async.
extern __shared__ char smem_raw[];

#define AS_BYTES (128 * 264 * 2)
#define CS_BYTES (128 * 264 * 2)
#define OFF_CS0  AS_BYTES
#define OFF_CS1  (AS_BYTES + CS_BYTES)
#define OFF_CLAB (AS_BYTES + 2 * CS_BYTES)              // two buffers of 128 ints
#define OFF_REDS (OFF_CLAB + 2 * 512)
#define OFF_REDP (OFF_REDS + 2048)
#define SMEM_BYTES (OFF_REDP + 2048)

__global__ void __launch_bounds__(512, 1) k_main() {
    float* redS = (float*)(smem_raw + OFF_REDS);         // [128][4]
    float* redP = (float*)(smem_raw + OFF_REDP);
    int*   clab_sm = (int*)(smem_raw + OFF_CLAB);        // [2][128]

    const int tid     = threadIdx.x;
    const int chunk   = blockIdx.x;
    const int rowbase = blockIdx.y * 128;
    const int lane = tid & 31;
    const int w    = tid >> 5;     // 0..15
    const int wr   = w >> 2;       // 0..3 (32-row group)
    const int wc   = w & 3;        // 0..3 (32-col group)
    const int g    = lane >> 2;
    const int t2   = (lane & 3) * 2;

    unsigned smu = (unsigned)__cvta_generic_to_shared(smem_raw);

    // A tile [128][256] via cp.async (4096 16B chunks / 512 threads = 8 iters)
    #pragma unroll
    for (int it = 0; it < 8; it++) {
        int lin = tid + it * 512;
        int row = lin >> 5;
        int kv  = lin & 31;
        cpasync16(smu + (row * 264 + kv * 8) * 2,
                  g_A + (size_t)(rowbase + row) * DIMS + kv * 8);
    }
    // first Cs subtile into buffer 0
    {
        const int colbase = chunk * 128;
        #pragma unroll
        for (int it = 0; it < 8; it++) {
            int lin = tid + it * 512;
            int row = lin >> 5;
            int kv  = lin & 31;
            cpasync16(smu + OFF_CS0 + (row * 264 + kv * 8) * 2,
                      g_C + (size_t)(colbase + row) * DIMS + kv * 8);
        }
        if (tid < 32) cpasync16(smu + OFF_CLAB + tid * 16, g_clab + colbase + tid * 4);
    }
    CP_COMMIT();

    // ldmatrix lane addresses
    unsigned aAddr[2], bOff[2];
    {
        int arow = (lane & 7) + ((lane >> 3) & 1) * 8;
        int acol = (lane >> 4) * 8;
        #pragma unroll
        for (int mb = 0; mb < 2; mb++)
            aAddr[mb] = smu + ((wr * 32 + mb * 16 + arow) * 264 + acol) * 2;
        int brow = ((lane >> 4) & 1) * 8 + (lane & 7);
        int bcol = ((lane >> 3) & 1) * 8;
        #pragma unroll
        for (int pr = 0; pr < 2; pr++)
            bOff[pr] = ((wc * 32 + pr * 16 + brow) * 264 + bcol) * 2;
    }

    float Sacc[2][2] = {{0.f, 0.f}, {0.f, 0.f}};
    float Pacc[2][2] = {{0.f, 0.f}, {0.f, 0.f}};
    int rlab[2][2], grow[2][2];
    #pragma unroll
    for (int mb = 0; mb < 2; mb++)
        #pragma unroll
        for (int p = 0; p < 2; p++) {
            int r = rowbase + wr * 32 + mb * 16 + g + 8 * p;
            grow[mb][p] = r;
            rlab[mb][p] = (r < NA) ? (r / KPC) : -2;
        }

    CP_WAIT0();
    __syncthreads();

    int i = 0;
    for (int s = chunk; s < NSUB128; s += COL_CHUNKS, i++) {
        const int colbase = s * 128;
        const int cur = i & 1;
        const unsigned csBase = smu + (cur ? OFF_CS1 : OFF_CS0);
        const bool edge = (colbase + 128 > NCOLS) || (colbase == rowbase);

        // prefetch next subtile into the other buffer (overlapped with MMA below)
        const int ns = s + COL_CHUNKS;
        if (ns < NSUB128) {
            const int ncb = ns * 128;
            const unsigned nxtBase = smu + (cur ? OFF_CS0 : OFF_CS1);
            #pragma unroll
            for (int it = 0; it < 8; it++) {
                int lin = tid + it * 512;
                int row = lin >> 5;
                int kv  = lin & 31;
                cpasync16(nxtBase + (row * 264 + kv * 8) * 2,
                          g_C + (size_t)(ncb + row) * DIMS + kv * 8);
            }
            if (tid < 32)
                cpasync16(smu + OFF_CLAB + (cur ^ 1) * 512 + tid * 16,
                          g_clab + ncb + tid * 4);
        }
        CP_COMMIT();

        float acc[2][4][4];
        #pragma unroll
        for (int mb = 0; mb < 2; mb++)
            #pragma unroll
            for (int nb = 0; nb < 4; nb++)
                #pragma unroll
                for (int q = 0; q < 4; q++) acc[mb][nb][q] = 0.f;

        #pragma unroll
        for (int k = 0; k < DIMS; k += 16) {
            unsigned a[2][4], b[4][2];
            #pragma unroll
            for (int mb = 0; mb < 2; mb++)
                ldsm_x4(a[mb][0], a[mb][1], a[mb][2], a[mb][3], aAddr[mb] + k * 2);
            #pragma unroll
            for (int pr = 0; pr < 2; pr++)
                ldsm_x4(b[2 * pr][0], b[2 * pr][1], b[2 * pr + 1][0], b[2 * pr + 1][1],
                        csBase + bOff[pr] + k * 2);
            #pragma unroll
            for (int mb = 0; mb < 2; mb++)
                #pragma unroll
                for (int nb = 0; nb < 4; nb++)
                    mma_bf16(acc[mb][nb], a[mb], b[nb]);
        }

        int labreg[8];
        #pragma unroll
        for (int nb = 0; nb < 4; nb++)
            #pragma unroll
            for (int e = 0; e < 2; e++)
                labreg[nb * 2 + e] = clab_sm[cur * 128 + wc * 32 + nb * 8 + t2 + e];

        if (!edge) {
            #pragma unroll
            for (int mb = 0; mb < 2; mb++)
                #pragma unroll
                for (int nb = 0; nb < 4; nb++)
                    #pragma unroll
                    for (int p = 0; p < 2; p++)
                        #pragma unroll
                        for (int e = 0; e < 2; e++)
                            ep_core(acc[mb][nb][2 * p + e], labreg[nb * 2 + e],
                                    rlab[mb][p], Sacc[mb][p], Pacc[mb][p]);
        } else {
            #pragma unroll
            for (int mb = 0; mb < 2; mb++)
                #pragma unroll
                for (int nb = 0; nb < 4; nb++) {
                    int colb = wc * 32 + nb * 8 + t2;
                    #pragma unroll
                    for (int p = 0; p < 2; p++)
                        #pragma unroll
                        for (int e = 0; e < 2; e++) {
                            int gcol = colbase + colb + e;
                            if (gcol < NCOLS && gcol != grow[mb][p])
                                ep_core(acc[mb][nb][2 * p + e], labreg[nb * 2 + e],
                                        rlab[mb][p], Sacc[mb][p], Pacc[mb][p]);
                        }
                }
        }

        CP_WAIT0();
        __syncthreads();    // all warps done with cur buffer; next buffer resident
    }

    #pragma unroll
    for (int mb = 0; mb < 2; mb++)
        #pragma unroll
        for (int p = 0; p < 2; p++) {
            float sv = Sacc[mb][p], pv = Pacc[mb][p];
            sv += __shfl_xor_sync(0xffffffffu, sv, 1);
            sv += __shfl_xor_sync(0xffffffffu, sv, 2);
            pv += __shfl_xor_sync(0xffffffffu, pv, 1);
            pv += __shfl_xor_sync(0xffffffffu, pv, 2);
            if ((lane & 3) == 0) {
                int row = wr * 32 + mb * 16 + g + 8 * p;
                redS[row * 4 + wc] = sv;
                redP[row * 4 + wc] = pv;
            }
        }
    __syncthreads();
    if (tid < 128) {
        int r = rowbase + tid;
        g_Sp[r * COL_CHUNKS + chunk] = redS[tid * 4] + redS[tid * 4 + 1] +
                                       redS[tid * 4 + 2] + redS[tid * 4 + 3];
        g_Pp[r * COL_CHUNKS + chunk] = redP[tid * 4] + redP[tid * 4 + 1] +
                                       redP[tid * 4 + 2] + redP[tid * 4 + 3];
    }
}

// -------------------- final scalar reduction --------------------
__global__ void k_final(const void* mlab, float* out) {
    __shared__ int scnt[NUM_CLASSES];
    __shared__ float wsum[32];
    int t = threadIdx.x;
    int lane = t & 31, wid = t >> 5;
    if (t < NUM_CLASSES) scnt[t] = 0;
    __syncthreads();
    for (int i = t; i < NMEM; i += 1024)
        atomicAdd(&scnt[load_label(mlab, i)], 1);
    __syncthreads();
    float local = 0.f;
    for (int n = t; n < NA; n += 1024) {
        float S = 0.f, P = 0.f;
        #pragma unroll
        for (int ch = 0; ch < COL_CHUNKS; ch++) {
            S += g_Sp[n * COL_CHUNKS + ch];
            P += g_Pp[n * COL_CHUNKS + ch];
        }
        float cnt = (float)(KPC - 1 + scnt[n / KPC]);
        local += (TEMP_INV * P - cnt * logf(S + 1e-12f)) / cnt;
    }
    #pragma unroll
    for (int o = 16; o; o >>= 1) local += __shfl_xor_sync(0xffffffffu, local, o);
    if (lane == 0) wsum[wid] = local;
    __syncthreads();
    if (t < 32) {
        float v = wsum[t];
        #pragma unroll
        for (int o = 16; o; o >>= 1) v += __shfl_xor_sync(0xffffffffu, v, o);
        if (t == 0) out[0] = -LOSS_SCALE * v / (float)NA;
    }
}

// -------------------- launch --------------------
extern "C" void kernel_launch(void* const* d_in, const int* in_sizes, int n_in,
                              void* d_out, int out_size) {
    (void)in_sizes; (void)n_in; (void)out_size;
    const float* pf   = (const float*)d_in[0];
    const void*  lab  = d_in[1];
    const float* mf   = (const float*)d_in[2];
    const void*  mlab = d_in[3];
    float* out = (float*)d_out;

    cudaFuncSetAttribute(k_main, cudaFuncAttributeMaxDynamicSharedMemorySize, SMEM_BYTES);

    k_sample<<<1, 1024>>>((const int*)lab, lab);
    k_anchor<<<NA_PAD / 8, 256>>>(pf);
    k_mem<<<(NC_PAD - NA + 7) / 8, 256>>>(mf, mlab);
    k_main<<<dim3(COL_CHUNKS, ROW_TILES), 512, SMEM_BYTES>>>();
    k_final<<<1, 1024>>>(mlab, out);
}

// round 14
// speedup vs baseline: 1.0474x; 1.0452x over previous
#include <cuda_runtime.h>
#include <cuda_bf16.h>
#include <math.h>
#include <stdint.h>

#define NUM_CLASSES 19
#define KPC 100
#define NA 1900
#define NA_PAD 1920
#define NMEM 20000
#define NCOLS 21900
#define NC_PAD 21952
#define DIMS 256
#define HW 16384
#define LBLK 1024
#define NLBLK 128
#define ROW_TILES 15
#define COL_CHUNKS 20
#define NSUB 343
#define NBLOCKS (COL_CHUNKS * ROW_TILES)
#define TEMP_INV 10.0f
#define L2E10 14.426950408889634f
#define LOSS_SCALE 1.4285714285714286f

// -------------------- device scratch --------------------
__device__ int g_lab64;
__device__ int g_idx[NA];
__device__ int g_cnt[NUM_CLASSES];
__device__ unsigned g_done;
__device__ __align__(16) __nv_bfloat16 g_A[NA_PAD * DIMS];
__device__ __align__(16) __nv_bfloat16 g_C[NC_PAD * DIMS];
__device__ int g_clab[NC_PAD];
__device__ float g_Sp[NA_PAD * COL_CHUNKS];
__device__ float g_Pp[NA_PAD * COL_CHUNKS];

__device__ __forceinline__ int load_label(const void* p, int i) {
    if (g_lab64) return (int)((const long long*)p)[i];
    return ((const int*)p)[i];
}

// MUFU-based exp-and-accumulate: S += 2^(acc*10*log2e), P += acc if labels match.
__device__ __forceinline__ void ep_core(float acc_v, int labv, int rl, float& S, float& P) {
    float e;
    asm("ex2.approx.f32 %0, %1;" : "=f"(e) : "f"(acc_v * L2E10));
    S += e;
    if (labv == rl) P += acc_v;
}

__device__ __forceinline__ void mma_bf16(float* d, const unsigned* a, const unsigned* b) {
    asm volatile(
        "mma.sync.aligned.m16n8k16.row.col.f32.bf16.bf16.f32 "
        "{%0,%1,%2,%3}, {%4,%5,%6,%7}, {%8,%9}, {%0,%1,%2,%3};\n"
        : "+f"(d[0]), "+f"(d[1]), "+f"(d[2]), "+f"(d[3])
        : "r"(a[0]), "r"(a[1]), "r"(a[2]), "r"(a[3]), "r"(b[0]), "r"(b[1]));
}

__device__ __forceinline__ void ldsm_x4(unsigned& r0, unsigned& r1, unsigned& r2,
                                        unsigned& r3, unsigned addr) {
    asm volatile("ldmatrix.sync.aligned.m8n8.x4.shared.b16 {%0,%1,%2,%3}, [%4];"
                 : "=r"(r0), "=r"(r1), "=r"(r2), "=r"(r3) : "r"(addr));
}

// -------------------- fused sampling + memory-label histogram ------------
__global__ void k_sample(const int* lab32, const void* labels, const void* mlab) {
    __shared__ int slab[LBLK];
    __shared__ int sbad;
    __shared__ int squit;
    __shared__ int scnt[NUM_CLASSES];
    int tid  = threadIdx.x;
    int lane = tid & 31;
    int w    = tid >> 5;

    if (tid == 0) sbad = 0;
    if (tid < NUM_CLASSES) scnt[tid] = 0;
    __syncthreads();
    if (lab32[2 * tid + 1] != 0) sbad = 1;
    __syncthreads();
    const int is64 = (sbad == 0) ? 1 : 0;
    if (tid == 0) g_lab64 = is64;

    // histogram of memory labels (for pos-count in the final reduction)
    for (int i = tid; i < NMEM; i += 1024) {
        int c = is64 ? (int)((const long long*)mlab)[i] : ((const int*)mlab)[i];
        atomicAdd(&scnt[c], 1);
    }

    int r = 0;
    unsigned below = (1u << lane) - 1u;

    for (int c = 0; c < NLBLK; c++) {
        int base = c * LBLK;
        int v;
        if (is64) v = (int)((const long long*)labels)[base + tid];
        else      v = ((const int*)labels)[base + tid];
        if (tid == 0) squit = 1;
        slab[tid] = v;
        __syncthreads();

        if (w < NUM_CLASSES && r < KPC) {
            #pragma unroll 4
            for (int s = 0; s < 32; s++) {
                int lv = slab[s * 32 + lane];
                unsigned m = __ballot_sync(0xffffffffu, lv == w);
                if (lv == w) {
                    int rank = r + __popc(m & below);
                    if (rank < KPC) g_idx[w * KPC + rank] = base + s * 32 + lane;
                }
                r += __popc(m);
                if (r >= KPC) break;
            }
        }
        if (w < NUM_CLASSES && lane == 0 && r < KPC) squit = 0;
        __syncthreads();
        if (squit) break;
    }
    __syncthreads();
    if (tid < NUM_CLASSES) g_cnt[tid] = scnt[tid];
}

// -------------------- fused gather/normalize: anchors + memory ------------
#define ANCHOR_BLOCKS (NA_PAD / 8)
#define MEM_BLOCKS ((NC_PAD - NA + 7) / 8)

__global__ void k_prep(const float* __restrict__ pf, const float* __restrict__ mf,
                       const void* mlab) {
    int wid  = threadIdx.x >> 5;
    int lane = threadIdx.x & 31;

    if (blockIdx.x < ANCHOR_BLOCKS) {
        int n = blockIdx.x * 8 + wid;
        float v[8];
        if (n < NA) {
            int idx = g_idx[n];
            int b   = idx >> 14;
            int rem = idx & (HW - 1);
            const float* src = pf + (size_t)b * (DIMS * HW) + rem;
            #pragma unroll
            for (int j = 0; j < 8; j++)
                v[j] = src[(size_t)(lane + 32 * j) * HW];
        } else {
            #pragma unroll
            for (int j = 0; j < 8; j++) v[j] = 0.f;
        }
        float ss = 0.f;
        #pragma unroll
        for (int j = 0; j < 8; j++) ss += v[j] * v[j];
        #pragma unroll
        for (int o = 16; o; o >>= 1) ss += __shfl_xor_sync(0xffffffffu, ss, o);
        float sc = (n < NA) ? (1.f / fmaxf(sqrtf(ss), 1e-12f)) : 0.f;
        #pragma unroll
        for (int j = 0; j < 8; j++) {
            __nv_bfloat16 o16 = __float2bfloat16(v[j] * sc);
            int d = lane + 32 * j;
            g_A[n * DIMS + d] = o16;
            g_C[n * DIMS + d] = o16;
        }
        if (lane == 0 && n < NA) g_clab[n] = n / KPC;
    } else {
        int m = (blockIdx.x - ANCHOR_BLOCKS) * 8 + wid;
        if (m >= NC_PAD - NA) return;
        float v[8];
        if (m < NMEM) {
            const float* src = mf + (size_t)m * DIMS;
            #pragma unroll
            for (int j = 0; j < 8; j++) v[j] = src[lane + 32 * j];
        } else {
            #pragma unroll
            for (int j = 0; j < 8; j++) v[j] = 0.f;
        }
        float ss = 0.f;
        #pragma unroll
        for (int j = 0; j < 8; j++) ss += v[j] * v[j];
        #pragma unroll
        for (int o = 16; o; o >>= 1) ss += __shfl_xor_sync(0xffffffffu, ss, o);
        float sc = (m < NMEM) ? (1.f / fmaxf(sqrtf(ss), 1e-12f)) : 0.f;
        #pragma unroll
        for (int j = 0; j < 8; j++)
            g_C[(size_t)(NA + m) * DIMS + lane + 32 * j] = __float2bfloat16(v[j] * sc);
        if (lane == 0)
            g_clab[NA + m] = (m < NMEM) ? load_label(mlab, m) : -1;
    }
}

// -------------------- fused GEMM + softmax reductions + last-block final ----
extern __shared__ char smem_raw[];

#define AS_BYTES (128 * 264 * 2)
#define CS_BYTES (64 * 264 * 2)
#define SMEM_BYTES (AS_BYTES + CS_BYTES + 64 * 4 + 2 * 256 * 4)

__global__ void __launch_bounds__(256) k_main(float* __restrict__ out) {
    __nv_bfloat16* As = (__nv_bfloat16*)smem_raw;                        // [128][264]
    __nv_bfloat16* Cs = (__nv_bfloat16*)(smem_raw + AS_BYTES);           // [64][264]
    int*   clab_sm = (int*)(smem_raw + AS_BYTES + CS_BYTES);             // [64]
    float* redS    = (float*)(smem_raw + AS_BYTES + CS_BYTES + 64 * 4);  // [128][2]
    float* redP    = redS + 256;

    const int tid     = threadIdx.x;
    const int chunk   = blockIdx.x;
    const int rowbase = blockIdx.y * 128;
    const int lane = tid & 31;
    const int w    = tid >> 5;
    const int wr   = w >> 1;
    const int wc   = w & 1;
    const int g    = lane >> 2;
    const int t2   = (lane & 3) * 2;

    const int ld_row = tid >> 5;
    const int ld_kv  = tid & 31;

    // A tile [128][256]
    #pragma unroll
    for (int it = 0; it < 16; it++) {
        int lin = tid + it * 256;
        int row = lin >> 5;
        int kv  = lin & 31;
        *(uint4*)(As + row * 264 + kv * 8) =
            *(const uint4*)(g_A + (size_t)(rowbase + row) * DIMS + kv * 8);
    }

    unsigned as_u32 = (unsigned)__cvta_generic_to_shared(As);
    unsigned cs_u32 = (unsigned)__cvta_generic_to_shared(Cs);
    unsigned aAddr[2], bAddr[2];
    {
        int arow = (lane & 7) + ((lane >> 3) & 1) * 8;
        int acol = (lane >> 4) * 8;
        #pragma unroll
        for (int mb = 0; mb < 2; mb++)
            aAddr[mb] = as_u32 + ((wr * 32 + mb * 16 + arow) * 264 + acol) * 2;
        int brow = ((lane >> 4) & 1) * 8 + (lane & 7);
        int bcol = ((lane >> 3) & 1) * 8;
        #pragma unroll
        for (int pr = 0; pr < 2; pr++)
            bAddr[pr] = cs_u32 + ((wc * 32 + pr * 16 + brow) * 264 + bcol) * 2;
    }

    float Sacc[2][2] = {{0.f, 0.f}, {0.f, 0.f}};
    float Pacc[2][2] = {{0.f, 0.f}, {0.f, 0.f}};
    int rlab[2][2], grow[2][2];
    #pragma unroll
    for (int mb = 0; mb < 2; mb++)
        #pragma unroll
        for (int p = 0; p < 2; p++) {
            int r = rowbase + wr * 32 + mb * 16 + g + 8 * p;
            grow[mb][p] = r;
            rlab[mb][p] = (r < NA) ? (r / KPC) : -2;
        }

    // prefetch first subtile into registers
    uint4 pre[8];
    int   prelab = 0;
    {
        const int colbase = chunk * 64;
        #pragma unroll
        for (int it = 0; it < 8; it++)
            pre[it] = *(const uint4*)(g_C + (size_t)(colbase + ld_row + it * 8) * DIMS + ld_kv * 8);
        if (tid < 64) prelab = g_clab[colbase + tid];
    }

    for (int s = chunk; s < NSUB; s += COL_CHUNKS) {
        const int colbase = s * 64;
        const bool edge = (colbase + 64 > NCOLS) ||
                          ((colbase < rowbase + 128) && (colbase + 64 > rowbase));
        __syncthreads();
        #pragma unroll
        for (int it = 0; it < 8; it++)
            *(uint4*)(Cs + (ld_row + it * 8) * 264 + ld_kv * 8) = pre[it];
        if (tid < 64) clab_sm[tid] = prelab;
        __syncthreads();

        const int ns = s + COL_CHUNKS;
        if (ns < NSUB) {
            const int ncb = ns * 64;
            #pragma unroll
            for (int it = 0; it < 8; it++)
                pre[it] = *(const uint4*)(g_C + (size_t)(ncb + ld_row + it * 8) * DIMS + ld_kv * 8);
            if (tid < 64) prelab = g_clab[ncb + tid];
        }

        float acc[2][4][4];
        #pragma unroll
        for (int mb = 0; mb < 2; mb++)
            #pragma unroll
            for (int nb = 0; nb < 4; nb++)
                #pragma unroll
                for (int q = 0; q < 4; q++) acc[mb][nb][q] = 0.f;

        #pragma unroll
        for (int k = 0; k < DIMS; k += 16) {
            unsigned a[2][4], b[4][2];
            #pragma unroll
            for (int mb = 0; mb < 2; mb++)
                ldsm_x4(a[mb][0], a[mb][1], a[mb][2], a[mb][3], aAddr[mb] + k * 2);
            #pragma unroll
            for (int pr = 0; pr < 2; pr++)
                ldsm_x4(b[2 * pr][0], b[2 * pr][1], b[2 * pr + 1][0], b[2 * pr + 1][1],
                        bAddr[pr] + k * 2);
            #pragma unroll
            for (int mb = 0; mb < 2; mb++)
                #pragma unroll
                for (int nb = 0; nb < 4; nb++)
                    mma_bf16(acc[mb][nb], a[mb], b[nb]);
        }

        int labreg[8];
        #pragma unroll
        for (int nb = 0; nb < 4; nb++)
            #pragma unroll
            for (int e = 0; e < 2; e++)
                labreg[nb * 2 + e] = clab_sm[wc * 32 + nb * 8 + t2 + e];

        if (!edge) {
            #pragma unroll
            for (int mb = 0; mb < 2; mb++)
                #pragma unroll
                for (int nb = 0; nb < 4; nb++)
                    #pragma unroll
                    for (int p = 0; p < 2; p++)
                        #pragma unroll
                        for (int e = 0; e < 2; e++)
                            ep_core(acc[mb][nb][2 * p + e], labreg[nb * 2 + e],
                                    rlab[mb][p], Sacc[mb][p], Pacc[mb][p]);
        } else {
            #pragma unroll
            for (int mb = 0; mb < 2; mb++)
                #pragma unroll
                for (int nb = 0; nb < 4; nb++) {
                    int colb = wc * 32 + nb * 8 + t2;
                    #pragma unroll
                    for (int p = 0; p < 2; p++)
                        #pragma unroll
                        for (int e = 0; e < 2; e++) {
                            int gcol = colbase + colb + e;
                            if (gcol < NCOLS && gcol != grow[mb][p])
                                ep_core(acc[mb][nb][2 * p + e], labreg[nb * 2 + e],
                                        rlab[mb][p], Sacc[mb][p], Pacc[mb][p]);
                        }
                }
        }
    }

    #pragma unroll
    for (int mb = 0; mb < 2; mb++)
        #pragma unroll
        for (int p = 0; p < 2; p++) {
            float sv = Sacc[mb][p], pv = Pacc[mb][p];
            sv += __shfl_xor_sync(0xffffffffu, sv, 1);
            sv += __shfl_xor_sync(0xffffffffu, sv, 2);
            pv += __shfl_xor_sync(0xffffffffu, pv, 1);
            pv += __shfl_xor_sync(0xffffffffu, pv, 2);
            if ((lane & 3) == 0) {
                int row = wr * 32 + mb * 16 + g + 8 * p;
                redS[row * 2 + wc] = sv;
                redP[row * 2 + wc] = pv;
            }
        }
    __syncthreads();
    if (tid < 128) {
        int r = rowbase + tid;
        g_Sp[r * COL_CHUNKS + chunk] = redS[tid * 2] + redS[tid * 2 + 1];
        g_Pp[r * COL_CHUNKS + chunk] = redP[tid * 2] + redP[tid * 2 + 1];
    }

    // ---- last-block final reduction ----
    __shared__ int sdone;
    __syncthreads();
    __threadfence();
    if (tid == 0) {
        unsigned v = atomicAdd(&g_done, 1u);
        sdone = (v == NBLOCKS - 1);
    }
    __syncthreads();
    if (!sdone) return;

    float local = 0.f;
    for (int n = tid; n < NA; n += 256) {
        float S = 0.f, P = 0.f;
        #pragma unroll
        for (int ch = 0; ch < COL_CHUNKS; ch++) {
            S += g_Sp[n * COL_CHUNKS + ch];
            P += g_Pp[n * COL_CHUNKS + ch];
        }
        float cnt = (float)(KPC - 1 + g_cnt[n / KPC]);
        local += (TEMP_INV * P - cnt * logf(S + 1e-12f)) / cnt;
    }
    redS[tid] = local;
    __syncthreads();
    for (int off = 128; off; off >>= 1) {
        if (tid < off) redS[tid] += redS[tid + off];
        __syncthreads();
    }
    if (tid == 0) {
        out[0] = -LOSS_SCALE * redS[0] / (float)NA;
        g_done = 0;                     // reset for next graph replay
    }
}

// -------------------- launch --------------------
extern "C" void kernel_launch(void* const* d_in, const int* in_sizes, int n_in,
                              void* d_out, int out_size) {
    (void)in_sizes; (void)n_in; (void)out_size;
    const float* pf   = (const float*)d_in[0];
    const void*  lab  = d_in[1];
    const float* mf   = (const float*)d_in[2];
    const void*  mlab = d_in[3];
    float* out = (float*)d_out;

    cudaFuncSetAttribute(k_main, cudaFuncAttributeMaxDynamicSharedMemorySize, SMEM_BYTES);

    k_sample<<<1, 1024>>>((const int*)lab, lab, mlab);
    k_prep<<<ANCHOR_BLOCKS + MEM_BLOCKS, 256>>>(pf, mf, mlab);
    k_main<<<dim3(COL_CHUNKS, ROW_TILES), 256, SMEM_BYTES>>>(out);
}